// round 12
// baseline (speedup 1.0000x reference)
#include <cuda_runtime.h>
#include <cuda_bf16.h>
#include <cstdint>

#define BB 8
#define SS 1024
#define DD 1024
#define HH 16
#define DH 64
#define KDIM 1024

// ---------------- scratch (__device__ globals; allocation-free rule) --------
__device__ __nv_bfloat16 g_qkvh[(size_t)8192 * 3072]; // qkv hi
__device__ __nv_bfloat16 g_qkvl[(size_t)8192 * 3072]; // qkv lo
__device__ __nv_bfloat16 g_ah[(size_t)8192 * 1024];   // attn-out hi
__device__ __nv_bfloat16 g_al[(size_t)8192 * 1024];   // attn-out lo
__device__ int8_t g_aq1[(size_t)8192 * 1024];         // activation int8 limb1
__device__ int8_t g_aq2[(size_t)8192 * 1024];         // activation int8 limb2
__device__ float  g_sa[8192];                         // activation row scales
__device__ int8_t g_wq1[3072 * 1024];                 // W_qkv^T int8 limb1 [N][K]
__device__ int8_t g_wq2[3072 * 1024];
__device__ float  g_swq[3072];
__device__ int8_t g_wo1[1024 * 1024];                 // W_out^T int8
__device__ int8_t g_wo2[1024 * 1024];
__device__ float  g_swo[1024];

// ---------------- helpers ---------------------------------------------------
__device__ __forceinline__ uint32_t smem_u32(const void* p) {
    uint32_t a;
    asm("{ .reg .u64 t; cvta.to.shared.u64 t, %1; cvt.u32.u64 %0, t; }"
        : "=r"(a) : "l"(p));
    return a;
}
#define LDSM_X4(r, addr)                                                        \
    asm volatile("ldmatrix.sync.aligned.m8n8.x4.shared.b16 {%0,%1,%2,%3}, [%4];"\
        : "=r"((r)[0]), "=r"((r)[1]), "=r"((r)[2]), "=r"((r)[3]) : "r"(addr))
#define LDSM_X2(r, addr)                                                        \
    asm volatile("ldmatrix.sync.aligned.m8n8.x2.shared.b16 {%0,%1}, [%2];"      \
        : "=r"((r)[0]), "=r"((r)[1]) : "r"(addr))
#define LDSM_X4_T(r, addr)                                                      \
    asm volatile("ldmatrix.sync.aligned.m8n8.x4.trans.shared.b16 {%0,%1,%2,%3}, [%4];"\
        : "=r"((r)[0]), "=r"((r)[1]), "=r"((r)[2]), "=r"((r)[3]) : "r"(addr))
// bf16 HMMA (attention)
#define MMA16816(d, a, b0, b1)                                                  \
    asm("mma.sync.aligned.m16n8k16.row.col.f32.bf16.bf16.f32 "                  \
        "{%0,%1,%2,%3}, {%4,%5,%6,%7}, {%8,%9}, {%0,%1,%2,%3};"                 \
        : "+f"((d)[0]), "+f"((d)[1]), "+f"((d)[2]), "+f"((d)[3])                \
        : "r"((a)[0]), "r"((a)[1]), "r"((a)[2]), "r"((a)[3]), "r"(b0), "r"(b1))
// int8 IMMA (GEMMs): 16x8x32, s32 accumulate
#define IMMA16832(d, a, b0, b1)                                                 \
    asm("mma.sync.aligned.m16n8k32.row.col.s32.s8.s8.s32 "                      \
        "{%0,%1,%2,%3}, {%4,%5,%6,%7}, {%8,%9}, {%0,%1,%2,%3};"                 \
        : "+r"((d)[0]), "+r"((d)[1]), "+r"((d)[2]), "+r"((d)[3])                \
        : "r"((a)[0]), "r"((a)[1]), "r"((a)[2]), "r"((a)[3]), "r"(b0), "r"(b1))
#define CP_ASYNC16(sa, gp)                                                      \
    asm volatile("cp.async.cg.shared.global [%0], [%1], 16;"                    \
                 :: "r"(sa), "l"(gp) : "memory")
#define CP_COMMIT() asm volatile("cp.async.commit_group;" ::: "memory")
#define CP_WAIT0()  asm volatile("cp.async.wait_group 0;" ::: "memory")
#define CP_WAIT1()  asm volatile("cp.async.wait_group 1;" ::: "memory")
#define CP_WAIT2()  asm volatile("cp.async.wait_group 2;" ::: "memory")

__device__ __forceinline__ uint32_t pack_bf16(__nv_bfloat16 a, __nv_bfloat16 b) {
    return (uint32_t)__bfloat16_as_ushort(a) | ((uint32_t)__bfloat16_as_ushort(b) << 16);
}
__device__ __forceinline__ void split1(float v, __nv_bfloat16& h, __nv_bfloat16& l) {
    h = __float2bfloat16(v);
    float hf = __uint_as_float(((uint32_t)__bfloat16_as_ushort(h)) << 16);
    l = __float2bfloat16(v - hf);
}
__device__ __forceinline__ void split2(float a, float b, uint32_t& h, uint32_t& l) {
    __nv_bfloat16 ha, la, hb, lb;
    split1(a, ha, la); split1(b, hb, lb);
    h = pack_bf16(ha, hb); l = pack_bf16(la, lb);
}
__device__ __forceinline__ float ex2(float x) {
    float r;
    asm("ex2.approx.f32 %0, %1;" : "=f"(r) : "f"(x));
    return r;
}
__device__ __forceinline__ float bfbits(uint32_t hw) {
    return __uint_as_float(hw << 16);
}

// ---------------------------------------------------------------------------
// Column max of W[K][N] -> scale S[n] = max/127
// ---------------------------------------------------------------------------
__global__ void __launch_bounds__(256)
colmax_kernel(const float* __restrict__ W, float* __restrict__ S, int K, int N) {
    __shared__ float red[8][32];
    const int tx = threadIdx.x & 31, ty = threadIdx.x >> 5;
    const int n = blockIdx.x * 32 + tx;
    float m = 0.f;
    for (int k = ty; k < K; k += 8)
        m = fmaxf(m, fabsf(W[(size_t)k * N + n]));
    red[ty][tx] = m;
    __syncthreads();
    if (ty == 0) {
#pragma unroll
        for (int i = 1; i < 8; i++) m = fmaxf(m, red[i][tx]);
        S[n] = fmaxf(m, 1e-30f) * (1.f / 127.f);
    }
}

// ---------------------------------------------------------------------------
// Weight quantize: W[K][N] fp32 -> Q1,Q2 [N][K] int8 (transpose + 2 limbs)
// ---------------------------------------------------------------------------
__global__ void __launch_bounds__(256)
wquant_kernel(const float* __restrict__ W, const float* __restrict__ S,
              int8_t* __restrict__ Q1, int8_t* __restrict__ Q2, int K, int N) {
    __shared__ float t[32][33];
    const int tx = threadIdx.x, ty = threadIdx.y;
    const int n0 = blockIdx.x * 32, k0 = blockIdx.y * 32;
#pragma unroll
    for (int i = 0; i < 32; i += 8)
        t[ty + i][tx] = W[(size_t)(k0 + ty + i) * N + n0 + tx];
    __syncthreads();
#pragma unroll
    for (int i = 0; i < 32; i += 8) {
        const int n = ty + i;
        const float rs = 1.f / S[n0 + n];
        const float q = t[tx][n] * rs;
        int a1 = __float2int_rn(q);
        int a2 = __float2int_rn((q - (float)a1) * 256.f);
        a2 = max(-127, min(127, a2));
        Q1[(size_t)(n0 + n) * K + k0 + tx] = (int8_t)a1;
        Q2[(size_t)(n0 + n) * K + k0 + tx] = (int8_t)a2;
    }
}

// ---------------------------------------------------------------------------
// Activation quantize (fp32 in): warp per row -> int8 limbs + row scale
// ---------------------------------------------------------------------------
__global__ void __launch_bounds__(256)
xquant_kernel(const float* __restrict__ X, int8_t* __restrict__ Q1,
              int8_t* __restrict__ Q2, float* __restrict__ S) {
    const int lane = threadIdx.x & 31;
    const int row = blockIdx.x * 8 + (threadIdx.x >> 5);
    const float4* xp = (const float4*)(X + (size_t)row * KDIM);
    float4 v[8];
    float m = 0.f;
#pragma unroll
    for (int i = 0; i < 8; i++) {
        v[i] = xp[lane + i * 32];
        m = fmaxf(m, fmaxf(fmaxf(fabsf(v[i].x), fabsf(v[i].y)),
                           fmaxf(fabsf(v[i].z), fabsf(v[i].w))));
    }
#pragma unroll
    for (int o = 16; o > 0; o >>= 1) m = fmaxf(m, __shfl_xor_sync(0xffffffffu, m, o));
    const float s = fmaxf(m, 1e-30f) * (1.f / 127.f);
    const float rs = 1.f / s;
    if (lane == 0) S[row] = s;
    uint32_t* q1 = (uint32_t*)(Q1 + (size_t)row * KDIM);
    uint32_t* q2 = (uint32_t*)(Q2 + (size_t)row * KDIM);
#pragma unroll
    for (int i = 0; i < 8; i++) {
        float f[4] = {v[i].x, v[i].y, v[i].z, v[i].w};
        uint32_t p1 = 0, p2 = 0;
#pragma unroll
        for (int j = 0; j < 4; j++) {
            const float q = f[j] * rs;
            int a1 = __float2int_rn(q);
            int a2 = __float2int_rn((q - (float)a1) * 256.f);
            a2 = max(-127, min(127, a2));
            p1 |= ((uint32_t)(uint8_t)(int8_t)a1) << (8 * j);
            p2 |= ((uint32_t)(uint8_t)(int8_t)a2) << (8 * j);
        }
        q1[lane + i * 32] = p1;
        q2[lane + i * 32] = p2;
    }
}

// ---------------------------------------------------------------------------
// Attn-output quantize (bf16 hi/lo in): warp per row
// ---------------------------------------------------------------------------
__global__ void __launch_bounds__(256)
oquant_kernel(const __nv_bfloat16* __restrict__ H, const __nv_bfloat16* __restrict__ L,
              int8_t* __restrict__ Q1, int8_t* __restrict__ Q2, float* __restrict__ S) {
    const int lane = threadIdx.x & 31;
    const int row = blockIdx.x * 8 + (threadIdx.x >> 5);
    const uint2* hp = (const uint2*)(H + (size_t)row * KDIM);
    const uint2* lp = (const uint2*)(L + (size_t)row * KDIM);
    float v[8][4];
    float m = 0.f;
#pragma unroll
    for (int i = 0; i < 8; i++) {
        uint2 hv = hp[lane + i * 32];
        uint2 lv = lp[lane + i * 32];
        v[i][0] = bfbits(hv.x & 0xffff) + bfbits(lv.x & 0xffff);
        v[i][1] = bfbits(hv.x >> 16)    + bfbits(lv.x >> 16);
        v[i][2] = bfbits(hv.y & 0xffff) + bfbits(lv.y & 0xffff);
        v[i][3] = bfbits(hv.y >> 16)    + bfbits(lv.y >> 16);
#pragma unroll
        for (int j = 0; j < 4; j++) m = fmaxf(m, fabsf(v[i][j]));
    }
#pragma unroll
    for (int o = 16; o > 0; o >>= 1) m = fmaxf(m, __shfl_xor_sync(0xffffffffu, m, o));
    const float s = fmaxf(m, 1e-30f) * (1.f / 127.f);
    const float rs = 1.f / s;
    if (lane == 0) S[row] = s;
    uint32_t* q1 = (uint32_t*)(Q1 + (size_t)row * KDIM);
    uint32_t* q2 = (uint32_t*)(Q2 + (size_t)row * KDIM);
#pragma unroll
    for (int i = 0; i < 8; i++) {
        uint32_t p1 = 0, p2 = 0;
#pragma unroll
        for (int j = 0; j < 4; j++) {
            const float q = v[i][j] * rs;
            int a1 = __float2int_rn(q);
            int a2 = __float2int_rn((q - (float)a1) * 256.f);
            a2 = max(-127, min(127, a2));
            p1 |= ((uint32_t)(uint8_t)(int8_t)a1) << (8 * j);
            p2 |= ((uint32_t)(uint8_t)(int8_t)a2) << (8 * j);
        }
        q1[lane + i * 32] = p1;
        q2[lane + i * 32] = p2;
    }
}

// ---------------------------------------------------------------------------
// IMMA GEMM (int8, 2 limbs, 3 terms / 2 accumulators):
//  C[m][n] = sa[m]*sw[n]*(hi + mid/256)
//  CTA 128x128, 8 warps (2x4) of 64x32, KC=64 int8, 2-stage cp.async.
//  Stage: A1(10240) A2(10240) B1(10240) B2(10240) = 40960 B, row stride 80 B.
// ---------------------------------------------------------------------------
#define KC 64
#define GRSTRIDE 80
#define G_OFF_A2 10240
#define G_OFF_B1 20480
#define G_OFF_B2 30720
#define GSTAGE 40960
#define GEMM_SMEM (2 * GSTAGE)
#define NCHUNK 16

template <bool SPLITOUT>
__global__ void __launch_bounds__(256, 1)
gemm_imma(const int8_t* __restrict__ A1, const int8_t* __restrict__ A2,
          const float* __restrict__ SA,
          const int8_t* __restrict__ W1, const int8_t* __restrict__ W2,
          const float* __restrict__ SW,
          float* __restrict__ C, __nv_bfloat16* __restrict__ Ch,
          __nv_bfloat16* __restrict__ Cl, int N) {
    extern __shared__ char smem[];
    const uint32_t sb = smem_u32(smem);
    const int tid = threadIdx.x;
    const int warp = tid >> 5, lane = tid & 31;
    const int m0 = blockIdx.y * 128, n0 = blockIdx.x * 128;
    const int wm = (warp >> 2) * 64;          // 0/64
    const int wn = (warp & 3) * 32;           // 0/32/64/96

    int32_t hi[4][4][4], mid[4][4][4];
#pragma unroll
    for (int mt = 0; mt < 4; mt++)
#pragma unroll
        for (int nt = 0; nt < 4; nt++)
#pragma unroll
            for (int i = 0; i < 4; i++) { hi[mt][nt][i] = 0; mid[mt][nt][i] = 0; }

    auto issue_stage = [&](int s) {
        const uint32_t so = sb + (uint32_t)(s & 1) * GSTAGE;
        const int k0 = s * KC;                 // int8 elements == bytes
#pragma unroll
        for (int i = 0; i < 2; i++) {
            const int idx = tid + i * 256;     // 0..511
            const int row = idx >> 2;          // 0..127
            const int cc = (idx & 3);          // 16B chunk within 64B row
            const uint32_t soff = so + (uint32_t)row * GRSTRIDE + (uint32_t)cc * 16;
            const size_t ga = (size_t)(m0 + row) * KDIM + k0 + cc * 16;
            const size_t gb = (size_t)(n0 + row) * KDIM + k0 + cc * 16;
            CP_ASYNC16(soff,            A1 + ga);
            CP_ASYNC16(soff + G_OFF_A2, A2 + ga);
            CP_ASYNC16(soff + G_OFF_B1, W1 + gb);
            CP_ASYNC16(soff + G_OFF_B2, W2 + gb);
        }
    };

    issue_stage(0); CP_COMMIT();
    issue_stage(1); CP_COMMIT();

#pragma unroll 1
    for (int c = 0; c < NCHUNK; c++) {
        if (c == NCHUNK - 1) { CP_WAIT0(); } else { CP_WAIT1(); }
        __syncthreads();

        const uint32_t cur = (uint32_t)(c & 1) * GSTAGE;
        const uint32_t abase = sb + cur + (uint32_t)(wm + (lane & 15)) * GRSTRIDE
                             + (uint32_t)(lane >> 4) * 16;
        const uint32_t bbase = sb + cur + G_OFF_B1 + (uint32_t)(wn + (lane & 7)) * GRSTRIDE
                             + (uint32_t)((lane >> 3) & 1) * 16;
#pragma unroll
        for (int k = 0; k < 2; k++) {          // two k32 steps per 64B chunk
            uint32_t a1f[4][4], a2f[4][4];
#pragma unroll
            for (int mt = 0; mt < 4; mt++) {
                const uint32_t aa = abase + mt * 16 * GRSTRIDE + k * 32;
                LDSM_X4(a1f[mt], aa);
                LDSM_X4(a2f[mt], aa + G_OFF_A2);
            }
#pragma unroll
            for (int nt = 0; nt < 4; nt++) {
                uint32_t b1[2], b2[2];
                const uint32_t ba = bbase + nt * 8 * GRSTRIDE + k * 32;
                LDSM_X2(b1, ba);
                LDSM_X2(b2, ba + (G_OFF_B2 - G_OFF_B1));
#pragma unroll
                for (int mt = 0; mt < 4; mt++)
                    IMMA16832(hi[mt][nt], a1f[mt], b1[0], b1[1]);
#pragma unroll
                for (int mt = 0; mt < 4; mt++)
                    IMMA16832(mid[mt][nt], a1f[mt], b2[0], b2[1]);
#pragma unroll
                for (int mt = 0; mt < 4; mt++)
                    IMMA16832(mid[mt][nt], a2f[mt], b1[0], b1[1]);
            }
        }
        __syncthreads();
        if (c + 2 < NCHUNK) { issue_stage(c + 2); CP_COMMIT(); }
    }

    // epilogue: dequantize + store
#pragma unroll
    for (int mt = 0; mt < 4; mt++) {
        const int row = m0 + wm + mt * 16 + (lane >> 2);
        const float sa0 = SA[row], sa1 = SA[row + 8];
#pragma unroll
        for (int nt = 0; nt < 4; nt++) {
            const int col = n0 + wn + nt * 8 + (lane & 3) * 2;
            const float swa = SW[col], swb = SW[col + 1];
            const float c0 = sa0 * swa * ((float)hi[mt][nt][0] + (float)mid[mt][nt][0] * (1.f / 256.f));
            const float c1 = sa0 * swb * ((float)hi[mt][nt][1] + (float)mid[mt][nt][1] * (1.f / 256.f));
            const float c2 = sa1 * swa * ((float)hi[mt][nt][2] + (float)mid[mt][nt][2] * (1.f / 256.f));
            const float c3 = sa1 * swb * ((float)hi[mt][nt][3] + (float)mid[mt][nt][3] * (1.f / 256.f));
            if (SPLITOUT) {
                uint32_t h01, l01, h23, l23;
                split2(c0, c1, h01, l01);
                split2(c2, c3, h23, l23);
                *(uint32_t*)(Ch + (size_t)row * N + col) = h01;
                *(uint32_t*)(Cl + (size_t)row * N + col) = l01;
                *(uint32_t*)(Ch + (size_t)(row + 8) * N + col) = h23;
                *(uint32_t*)(Cl + (size_t)(row + 8) * N + col) = l23;
            } else {
                *(float2*)(C + (size_t)row * N + col) = make_float2(c0, c1);
                *(float2*)(C + (size_t)(row + 8) * N + col) = make_float2(c2, c3);
            }
        }
    }
}

// ---------------------------------------------------------------------------
// HMMA causal flash attention (R9/R11 bf16 3-term, proven).
// ---------------------------------------------------------------------------
#define RSTRIDE 144
#define A_OFF_QH 0
#define A_OFF_QL 18432
#define A_KV0 36864
#define A_KVSTAGE 36864          // Kh(9216) Kl(9216) Vh(9216) Vl(9216)
#define ATT_SMEM (A_KV0 + 3 * A_KVSTAGE)

__global__ void __launch_bounds__(256, 1)
attn_mma(const __nv_bfloat16* __restrict__ qkvh, const __nv_bfloat16* __restrict__ qkvl,
         __nv_bfloat16* __restrict__ Oh, __nv_bfloat16* __restrict__ Ol) {
    extern __shared__ char smem[];
    const uint32_t sb = smem_u32(smem);
    const int tid = threadIdx.x;
    const int warp = tid >> 5, lane = tid & 31;
    const int qt = 7 - blockIdx.x;
    const int b = blockIdx.y >> 4, h = blockIdx.y & 15;
    const int qrow0 = qt * 128;
    const size_t rowbase = (size_t)b * SS;
    const int jlast = 2 * qt + 1;

#pragma unroll
    for (int i = 0; i < 4; i++) {
        const int idx = tid + i * 256;
        const int row = idx >> 3;
        const int c8 = (idx & 7) * 8;
        const size_t g = (rowbase + qrow0 + row) * 3072 + h * DH + c8;
        const uint32_t so = sb + (uint32_t)row * RSTRIDE + (uint32_t)c8 * 2;
        CP_ASYNC16(so + A_OFF_QH, qkvh + g);
        CP_ASYNC16(so + A_OFF_QL, qkvl + g);
    }
    auto issue_kv = [&](int j) {
        const uint32_t so = sb + A_KV0 + (uint32_t)(j % 3) * A_KVSTAGE;
#pragma unroll
        for (int i = 0; i < 2; i++) {
            const int idx = tid + i * 256;
            const int row = idx >> 3;
            const int c8 = (idx & 7) * 8;
            const size_t g = (rowbase + j * 64 + row) * 3072 + h * DH + c8;
            const uint32_t soff = so + (uint32_t)row * RSTRIDE + (uint32_t)c8 * 2;
            CP_ASYNC16(soff,         qkvh + g + 1024);
            CP_ASYNC16(soff + 9216,  qkvl + g + 1024);
            CP_ASYNC16(soff + 18432, qkvh + g + 2048);
            CP_ASYNC16(soff + 27648, qkvl + g + 2048);
        }
    };
    issue_kv(0); CP_COMMIT();
    if (jlast >= 1) { issue_kv(1); CP_COMMIT(); }

    if (jlast >= 1) { CP_WAIT1(); } else { CP_WAIT0(); }
    __syncthreads();

    uint32_t qh[4][4], ql[4][4];
    {
        const uint32_t qbase = sb + (uint32_t)(warp * 16 + (lane & 15)) * RSTRIDE
                             + (uint32_t)(lane >> 4) * 16;
#pragma unroll
        for (int ks = 0; ks < 4; ks++) {
            LDSM_X4(qh[ks], qbase + A_OFF_QH + ks * 32);
            LDSM_X4(ql[ks], qbase + A_OFF_QL + ks * 32);
        }
    }

    float O[8][4];
#pragma unroll
    for (int dt = 0; dt < 8; dt++)
#pragma unroll
        for (int i = 0; i < 4; i++) O[dt][i] = 0.f;
    float m0 = -1e30f, m1 = -1e30f, l0 = 0.f, l1 = 0.f;

    const int rg0 = qrow0 + warp * 16 + (lane >> 2);
    const float SC = 0.18033688011112042f;     // (1/8) * log2(e)

#pragma unroll 1
    for (int j = 0; j <= jlast; j++) {
        if (j + 2 <= jlast) { issue_kv(j + 2); CP_COMMIT(); }
        if (j + 2 <= jlast)      { CP_WAIT2(); }
        else if (j + 1 <= jlast) { CP_WAIT1(); }
        else                     { CP_WAIT0(); }
        __syncthreads();

        const bool active = (64 * j) <= (qrow0 + warp * 16 + 15);
        if (active) {
            const uint32_t so = sb + A_KV0 + (uint32_t)(j % 3) * A_KVSTAGE;

            float S[8][4];
#pragma unroll
            for (int nt = 0; nt < 8; nt++)
#pragma unroll
                for (int i = 0; i < 4; i++) S[nt][i] = 0.f;

            const uint32_t kbase = so + (uint32_t)(lane & 7) * RSTRIDE
                                 + (uint32_t)(lane >> 3) * 16;
#pragma unroll
            for (int nt = 0; nt < 8; nt++) {
                const uint32_t ka = kbase + nt * 8 * RSTRIDE;
                uint32_t kh0[4], kh1[4], kl0[4], kl1[4];
                LDSM_X4(kh0, ka);          LDSM_X4(kh1, ka + 64);
                LDSM_X4(kl0, ka + 9216);   LDSM_X4(kl1, ka + 9216 + 64);
                MMA16816(S[nt], qh[0], kh0[0], kh0[1]);
                MMA16816(S[nt], qh[1], kh0[2], kh0[3]);
                MMA16816(S[nt], qh[2], kh1[0], kh1[1]);
                MMA16816(S[nt], qh[3], kh1[2], kh1[3]);
                MMA16816(S[nt], qh[0], kl0[0], kl0[1]);
                MMA16816(S[nt], qh[1], kl0[2], kl0[3]);
                MMA16816(S[nt], qh[2], kl1[0], kl1[1]);
                MMA16816(S[nt], qh[3], kl1[2], kl1[3]);
                MMA16816(S[nt], ql[0], kh0[0], kh0[1]);
                MMA16816(S[nt], ql[1], kh0[2], kh0[3]);
                MMA16816(S[nt], ql[2], kh1[0], kh1[1]);
                MMA16816(S[nt], ql[3], kh1[2], kh1[3]);
            }

            const bool needmask = (j >= 2 * qt);
            float mx0 = -1e30f, mx1 = -1e30f;
#pragma unroll
            for (int nt = 0; nt < 8; nt++) {
                float t0 = S[nt][0] * SC, t1 = S[nt][1] * SC;
                float t2 = S[nt][2] * SC, t3 = S[nt][3] * SC;
                if (needmask) {
                    const int col = 64 * j + 8 * nt + 2 * (lane & 3);
                    if (col > rg0)         t0 = -1e30f;
                    if (col + 1 > rg0)     t1 = -1e30f;
                    if (col > rg0 + 8)     t2 = -1e30f;
                    if (col + 1 > rg0 + 8) t3 = -1e30f;
                }
                S[nt][0] = t0; S[nt][1] = t1; S[nt][2] = t2; S[nt][3] = t3;
                mx0 = fmaxf(mx0, fmaxf(t0, t1));
                mx1 = fmaxf(mx1, fmaxf(t2, t3));
            }
            mx0 = fmaxf(mx0, __shfl_xor_sync(0xffffffffu, mx0, 1));
            mx0 = fmaxf(mx0, __shfl_xor_sync(0xffffffffu, mx0, 2));
            mx1 = fmaxf(mx1, __shfl_xor_sync(0xffffffffu, mx1, 1));
            mx1 = fmaxf(mx1, __shfl_xor_sync(0xffffffffu, mx1, 2));

            const float mn0 = fmaxf(m0, mx0), mn1 = fmaxf(m1, mx1);
            const float cr0 = ex2(m0 - mn0), cr1 = ex2(m1 - mn1);
            m0 = mn0; m1 = mn1;

            float ls0 = 0.f, ls1 = 0.f;
#pragma unroll
            for (int nt = 0; nt < 8; nt++) {
                const float p0 = ex2(S[nt][0] - m0), p1 = ex2(S[nt][1] - m0);
                const float p2 = ex2(S[nt][2] - m1), p3 = ex2(S[nt][3] - m1);
                S[nt][0] = p0; S[nt][1] = p1; S[nt][2] = p2; S[nt][3] = p3;
                ls0 += p0 + p1;
                ls1 += p2 + p3;
            }
            ls0 += __shfl_xor_sync(0xffffffffu, ls0, 1);
            ls0 += __shfl_xor_sync(0xffffffffu, ls0, 2);
            ls1 += __shfl_xor_sync(0xffffffffu, ls1, 1);
            ls1 += __shfl_xor_sync(0xffffffffu, ls1, 2);
            l0 = l0 * cr0 + ls0;
            l1 = l1 * cr1 + ls1;

#pragma unroll
            for (int dt = 0; dt < 8; dt++) {
                O[dt][0] *= cr0; O[dt][1] *= cr0;
                O[dt][2] *= cr1; O[dt][3] *= cr1;
            }

            uint32_t ph[4][4], pl[4][4];
#pragma unroll
            for (int ks = 0; ks < 4; ks++) {
                split2(S[2 * ks][0],     S[2 * ks][1],     ph[ks][0], pl[ks][0]);
                split2(S[2 * ks][2],     S[2 * ks][3],     ph[ks][1], pl[ks][1]);
                split2(S[2 * ks + 1][0], S[2 * ks + 1][1], ph[ks][2], pl[ks][2]);
                split2(S[2 * ks + 1][2], S[2 * ks + 1][3], ph[ks][3], pl[ks][3]);
            }

            const uint32_t vbase = so + 18432 + (uint32_t)lane * RSTRIDE;
#pragma unroll
            for (int dt = 0; dt < 8; dt++) {
                const uint32_t va = vbase + dt * 16;
                uint32_t vh0[4], vh1[4], vl0[4], vl1[4];
                LDSM_X4_T(vh0, va);                 LDSM_X4_T(vh1, va + 32 * RSTRIDE);
                LDSM_X4_T(vl0, va + 9216);          LDSM_X4_T(vl1, va + 9216 + 32 * RSTRIDE);
                MMA16816(O[dt], ph[0], vh0[0], vh0[1]);
                MMA16816(O[dt], ph[1], vh0[2], vh0[3]);
                MMA16816(O[dt], ph[2], vh1[0], vh1[1]);
                MMA16816(O[dt], ph[3], vh1[2], vh1[3]);
                MMA16816(O[dt], ph[0], vl0[0], vl0[1]);
                MMA16816(O[dt], ph[1], vl0[2], vl0[3]);
                MMA16816(O[dt], ph[2], vl1[0], vl1[1]);
                MMA16816(O[dt], ph[3], vl1[2], vl1[3]);
                MMA16816(O[dt], pl[0], vh0[0], vh0[1]);
                MMA16816(O[dt], pl[1], vh0[2], vh0[3]);
                MMA16816(O[dt], pl[2], vh1[0], vh1[1]);
                MMA16816(O[dt], pl[3], vh1[2], vh1[3]);
            }
        }
        __syncthreads();
    }

    const float inv0 = 1.f / l0, inv1 = 1.f / l1;
    const size_t row0 = rowbase + qrow0 + warp * 16 + (lane >> 2);
    const size_t row1 = row0 + 8;
#pragma unroll
    for (int dt = 0; dt < 8; dt++) {
        const int col = h * DH + dt * 8 + 2 * (lane & 3);
        uint32_t h01, l01, h23, l23;
        split2(O[dt][0] * inv0, O[dt][1] * inv0, h01, l01);
        split2(O[dt][2] * inv1, O[dt][3] * inv1, h23, l23);
        *(uint32_t*)(Oh + row0 * DD + col) = h01;
        *(uint32_t*)(Ol + row0 * DD + col) = l01;
        *(uint32_t*)(Oh + row1 * DD + col) = h23;
        *(uint32_t*)(Ol + row1 * DD + col) = l23;
    }
}

// ---------------------------------------------------------------------------
extern "C" void kernel_launch(void* const* d_in, const int* in_sizes, int n_in,
                              void* d_out, int out_size) {
    const float* x     = (const float*)d_in[0];   // [8,1024,1024]
    const float* w_qkv = (const float*)d_in[2];   // [1024,3072]
    const float* w_out = (const float*)d_in[3];   // [1024,1024]
    float* out = (float*)d_out;

    __nv_bfloat16 *qkvh, *qkvl, *ah, *al;
    int8_t *aq1, *aq2, *wq1, *wq2, *wo1, *wo2;
    float *sa, *swq, *swo;
    cudaGetSymbolAddress((void**)&qkvh, g_qkvh);
    cudaGetSymbolAddress((void**)&qkvl, g_qkvl);
    cudaGetSymbolAddress((void**)&ah, g_ah);
    cudaGetSymbolAddress((void**)&al, g_al);
    cudaGetSymbolAddress((void**)&aq1, g_aq1);
    cudaGetSymbolAddress((void**)&aq2, g_aq2);
    cudaGetSymbolAddress((void**)&wq1, g_wq1);
    cudaGetSymbolAddress((void**)&wq2, g_wq2);
    cudaGetSymbolAddress((void**)&wo1, g_wo1);
    cudaGetSymbolAddress((void**)&wo2, g_wo2);
    cudaGetSymbolAddress((void**)&sa, g_sa);
    cudaGetSymbolAddress((void**)&swq, g_swq);
    cudaGetSymbolAddress((void**)&swo, g_swo);

    cudaFuncSetAttribute(gemm_imma<true>,  cudaFuncAttributeMaxDynamicSharedMemorySize, GEMM_SMEM);
    cudaFuncSetAttribute(gemm_imma<false>, cudaFuncAttributeMaxDynamicSharedMemorySize, GEMM_SMEM);
    cudaFuncSetAttribute(attn_mma, cudaFuncAttributeMaxDynamicSharedMemorySize, ATT_SMEM);

    // 0) quantize weights (colmax -> transpose+2-limb) and activations
    colmax_kernel<<<3072 / 32, 256>>>(w_qkv, swq, 1024, 3072);
    colmax_kernel<<<1024 / 32, 256>>>(w_out, swo, 1024, 1024);
    wquant_kernel<<<dim3(3072 / 32, 1024 / 32), dim3(32, 8)>>>(w_qkv, swq, wq1, wq2, 1024, 3072);
    wquant_kernel<<<dim3(1024 / 32, 1024 / 32), dim3(32, 8)>>>(w_out, swo, wo1, wo2, 1024, 1024);
    xquant_kernel<<<8192 / 8, 256>>>(x, aq1, aq2, sa);

    // 1) QKV projection (int8 IMMA) -> split bf16 qkv for attention
    gemm_imma<true><<<dim3(3072 / 128, 8192 / 128), 256, GEMM_SMEM>>>(
        aq1, aq2, sa, wq1, wq2, swq, nullptr, qkvh, qkvl, 3072);

    // 2) causal flash attention (bf16 HMMA) -> split bf16 O
    attn_mma<<<dim3(8, BB * HH), 256, ATT_SMEM>>>(qkvh, qkvl, ah, al);

    // 3) quantize O, output projection (int8 IMMA) -> fp32 out
    oquant_kernel<<<8192 / 8, 256>>>(ah, al, aq1, aq2, sa);
    gemm_imma<false><<<dim3(1024 / 128, 8192 / 128), 256, GEMM_SMEM>>>(
        aq1, aq2, sa, wo1, wo2, swo, out, nullptr, nullptr, 1024);
}

// round 14
// speedup vs baseline: 2.3265x; 2.3265x over previous
#include <cuda_runtime.h>
#include <cuda_bf16.h>
#include <cstdint>

#define BB 8
#define SS 1024
#define DD 1024
#define HH 16
#define DH 64
#define KDIM 1024

// ---------------- scratch (__device__ globals; allocation-free rule) --------
__device__ __nv_bfloat16 g_qkvh[(size_t)8192 * 3072]; // qkv hi
__device__ __nv_bfloat16 g_qkvl[(size_t)8192 * 3072]; // qkv lo
__device__ __nv_bfloat16 g_wqkv_h[3072 * 1024];       // W_qkv^T hi [N][K]
__device__ __nv_bfloat16 g_wqkv_l[3072 * 1024];
__device__ __nv_bfloat16 g_wout_h[1024 * 1024];       // W_out^T hi
__device__ __nv_bfloat16 g_wout_l[1024 * 1024];
__device__ __nv_bfloat16 g_ah[(size_t)8192 * 1024];   // activation / attn-out hi
__device__ __nv_bfloat16 g_al[(size_t)8192 * 1024];   // activation / attn-out lo

// ---------------- helpers ---------------------------------------------------
__device__ __forceinline__ uint32_t smem_u32(const void* p) {
    uint32_t a;
    asm("{ .reg .u64 t; cvta.to.shared.u64 t, %1; cvt.u32.u64 %0, t; }"
        : "=r"(a) : "l"(p));
    return a;
}
#define LDSM_X4(r, addr)                                                        \
    asm volatile("ldmatrix.sync.aligned.m8n8.x4.shared.b16 {%0,%1,%2,%3}, [%4];"\
        : "=r"((r)[0]), "=r"((r)[1]), "=r"((r)[2]), "=r"((r)[3]) : "r"(addr))
#define LDSM_X2(r, addr)                                                        \
    asm volatile("ldmatrix.sync.aligned.m8n8.x2.shared.b16 {%0,%1}, [%2];"      \
        : "=r"((r)[0]), "=r"((r)[1]) : "r"(addr))
#define LDSM_X4_T(r, addr)                                                      \
    asm volatile("ldmatrix.sync.aligned.m8n8.x4.trans.shared.b16 {%0,%1,%2,%3}, [%4];"\
        : "=r"((r)[0]), "=r"((r)[1]), "=r"((r)[2]), "=r"((r)[3]) : "r"(addr))
#define MMA16816(d, a, b0, b1)                                                  \
    asm volatile("mma.sync.aligned.m16n8k16.row.col.f32.bf16.bf16.f32 "         \
        "{%0,%1,%2,%3}, {%4,%5,%6,%7}, {%8,%9}, {%0,%1,%2,%3};"                 \
        : "+f"((d)[0]), "+f"((d)[1]), "+f"((d)[2]), "+f"((d)[3])                \
        : "r"((a)[0]), "r"((a)[1]), "r"((a)[2]), "r"((a)[3]), "r"(b0), "r"(b1))
#define CP_ASYNC16(sa, gp)                                                      \
    asm volatile("cp.async.cg.shared.global [%0], [%1], 16;"                    \
                 :: "r"(sa), "l"(gp) : "memory")
#define CP_COMMIT() asm volatile("cp.async.commit_group;" ::: "memory")
#define CP_WAIT0()  asm volatile("cp.async.wait_group 0;" ::: "memory")
#define CP_WAIT1()  asm volatile("cp.async.wait_group 1;" ::: "memory")
#define CP_WAIT2()  asm volatile("cp.async.wait_group 2;" ::: "memory")

__device__ __forceinline__ uint32_t pack_bf16(__nv_bfloat16 a, __nv_bfloat16 b) {
    return (uint32_t)__bfloat16_as_ushort(a) | ((uint32_t)__bfloat16_as_ushort(b) << 16);
}
__device__ __forceinline__ void split1(float v, __nv_bfloat16& h, __nv_bfloat16& l) {
    h = __float2bfloat16(v);
    float hf = __uint_as_float(((uint32_t)__bfloat16_as_ushort(h)) << 16);
    l = __float2bfloat16(v - hf);
}
__device__ __forceinline__ void split2(float a, float b, uint32_t& h, uint32_t& l) {
    __nv_bfloat16 ha, la, hb, lb;
    split1(a, ha, la); split1(b, hb, lb);
    h = pack_bf16(ha, hb); l = pack_bf16(la, lb);
}
__device__ __forceinline__ float ex2(float x) {
    float r;
    asm("ex2.approx.f32 %0, %1;" : "=f"(r) : "f"(x));
    return r;
}

// ---------------------------------------------------------------------------
// Weight pre-pass: W[K,N] fp32 -> H,L [N,K] bf16 (transpose + hi/lo split)
// ---------------------------------------------------------------------------
__global__ void __launch_bounds__(256)
wsplit_kernel(const float* __restrict__ W, __nv_bfloat16* __restrict__ H,
              __nv_bfloat16* __restrict__ L, int K, int N) {
    __shared__ float t[32][33];
    const int tx = threadIdx.x, ty = threadIdx.y;
    const int n0 = blockIdx.x * 32, k0 = blockIdx.y * 32;
#pragma unroll
    for (int i = 0; i < 32; i += 8)
        t[ty + i][tx] = W[(size_t)(k0 + ty + i) * N + n0 + tx];
    __syncthreads();
#pragma unroll
    for (int i = 0; i < 32; i += 8) {
        const int n = ty + i;
        float v = t[tx][n];
        __nv_bfloat16 h, l;
        split1(v, h, l);
        H[(size_t)(n0 + n) * K + k0 + tx] = h;
        L[(size_t)(n0 + n) * K + k0 + tx] = l;
    }
}

// ---------------------------------------------------------------------------
// Activation split: X fp32 [M][K] -> H,L bf16 same layout (elementwise)
// ---------------------------------------------------------------------------
__global__ void __launch_bounds__(256)
xsplit_kernel(const float* __restrict__ X, __nv_bfloat16* __restrict__ H,
              __nv_bfloat16* __restrict__ L) {
    const size_t i4 = (size_t)blockIdx.x * 256 + threadIdx.x;
    float4 v = *(const float4*)(X + i4 * 4);
    __nv_bfloat16 h0, h1, h2, h3, l0, l1, l2, l3;
    split1(v.x, h0, l0); split1(v.y, h1, l1);
    split1(v.z, h2, l2); split1(v.w, h3, l3);
    *(uint2*)(H + i4 * 4) = make_uint2(pack_bf16(h0, h1), pack_bf16(h2, h3));
    *(uint2*)(L + i4 * 4) = make_uint2(pack_bf16(l0, l1), pack_bf16(l2, l3));
}

// ---------------------------------------------------------------------------
// HMMA GEMM (bf16 3-term), templated on CTA N-tile BN (192 or 256).
// 256 threads, 8 warps (2x4), warp tile 64 x (BN/4), KC=64, 2-stage pipeline.
// Stage: Ah/Al 128x144B, Bh/Bl BNx144B.
// ---------------------------------------------------------------------------
#define KC 64
#define RSTRIDE 144
#define NCHUNK 16

template <int BN, bool SPLITOUT>
__global__ void __launch_bounds__(256, 1)
gemm_mma(const __nv_bfloat16* __restrict__ Ah, const __nv_bfloat16* __restrict__ Al,
         const __nv_bfloat16* __restrict__ Wh, const __nv_bfloat16* __restrict__ Wl,
         float* __restrict__ C, __nv_bfloat16* __restrict__ Ch,
         __nv_bfloat16* __restrict__ Cl, int N) {
    constexpr int ABYTES = 128 * RSTRIDE;            // 18432
    constexpr int BBYTES = BN * RSTRIDE;             // 27648 / 36864
    constexpr int OFF_AL = ABYTES;
    constexpr int OFF_BH = 2 * ABYTES;
    constexpr int OFF_BL = 2 * ABYTES + BBYTES;
    constexpr int STAGE = 2 * ABYTES + 2 * BBYTES;
    constexpr int NT = BN / 32;                      // n-subtiles per warp (6 or 8)

    extern __shared__ char smem[];
    const uint32_t sb = smem_u32(smem);
    const int tid = threadIdx.x;
    const int warp = tid >> 5, lane = tid & 31;
    const int m0 = blockIdx.y * 128, n0 = blockIdx.x * BN;
    const int wm = (warp >> 2) * 64;                 // 0/64
    const int wn = (warp & 3) * (BN / 4);            // stride 48 or 64

    float acc[4][NT][4];
#pragma unroll
    for (int mt = 0; mt < 4; mt++)
#pragma unroll
        for (int nt = 0; nt < NT; nt++)
#pragma unroll
            for (int i = 0; i < 4; i++) acc[mt][nt][i] = 0.f;

    auto issue_stage = [&](int s) {
        const uint32_t so = sb + (uint32_t)(s & 1) * STAGE;
        const int k0 = s * KC;
#pragma unroll
        for (int i = 0; i < 4; i++) {
            const int idx = tid + i * 256;           // 0..1023 (A: 128 rows x 8)
            const int row = idx >> 3;
            const int k8 = (idx & 7) * 8;
            const uint32_t soff = so + (uint32_t)row * RSTRIDE + (uint32_t)k8 * 2;
            const size_t ga = (size_t)(m0 + row) * KDIM + k0 + k8;
            CP_ASYNC16(soff,          Ah + ga);
            CP_ASYNC16(soff + OFF_AL, Al + ga);
        }
#pragma unroll
        for (int i = 0; i < BN / 32; i++) {
            const int idx = tid + i * 256;           // B: BN rows x 8
            const int row = idx >> 3;
            const int k8 = (idx & 7) * 8;
            const uint32_t soff = so + OFF_BH + (uint32_t)row * RSTRIDE + (uint32_t)k8 * 2;
            const size_t gb = (size_t)(n0 + row) * KDIM + k0 + k8;
            CP_ASYNC16(soff, Wh + gb);
            CP_ASYNC16(soff + BBYTES, Wl + gb);
        }
    };

    issue_stage(0); CP_COMMIT();
    issue_stage(1); CP_COMMIT();

#pragma unroll 1
    for (int c = 0; c < NCHUNK; c++) {
        if (c == NCHUNK - 1) { CP_WAIT0(); } else { CP_WAIT1(); }
        __syncthreads();

        const uint32_t cur = (uint32_t)(c & 1) * STAGE;
        const uint32_t abase = sb + cur + (uint32_t)(wm + (lane & 15)) * RSTRIDE
                             + (uint32_t)(lane >> 4) * 16;
        const uint32_t bbase = sb + cur + OFF_BH + (uint32_t)(wn + (lane & 7)) * RSTRIDE
                             + (uint32_t)((lane >> 3) & 1) * 16;
#pragma unroll
        for (int k16 = 0; k16 < 4; k16++) {
            uint32_t ah4[4][4], al4[4][4];
#pragma unroll
            for (int mt = 0; mt < 4; mt++) {
                const uint32_t aa = abase + mt * 16 * RSTRIDE + k16 * 32;
                LDSM_X4(ah4[mt], aa);
                LDSM_X4(al4[mt], aa + OFF_AL);
            }
#pragma unroll
            for (int nt = 0; nt < NT; nt++) {
                uint32_t bh2[2], bl2[2];
                const uint32_t ba = bbase + nt * 8 * RSTRIDE + k16 * 32;
                LDSM_X2(bh2, ba);
                LDSM_X2(bl2, ba + BBYTES);
#pragma unroll
                for (int mt = 0; mt < 4; mt++) {
                    MMA16816(acc[mt][nt], ah4[mt], bh2[0], bh2[1]);
                    MMA16816(acc[mt][nt], ah4[mt], bl2[0], bl2[1]);
                    MMA16816(acc[mt][nt], al4[mt], bh2[0], bh2[1]);
                }
            }
        }
        __syncthreads();
        if (c + 2 < NCHUNK) { issue_stage(c + 2); CP_COMMIT(); }
    }

#pragma unroll
    for (int mt = 0; mt < 4; mt++) {
        const int row = m0 + wm + mt * 16 + (lane >> 2);
#pragma unroll
        for (int nt = 0; nt < NT; nt++) {
            const int col = n0 + wn + nt * 8 + (lane & 3) * 2;
            if (SPLITOUT) {
                uint32_t h01, l01, h23, l23;
                split2(acc[mt][nt][0], acc[mt][nt][1], h01, l01);
                split2(acc[mt][nt][2], acc[mt][nt][3], h23, l23);
                *(uint32_t*)(Ch + (size_t)row * N + col) = h01;
                *(uint32_t*)(Cl + (size_t)row * N + col) = l01;
                *(uint32_t*)(Ch + (size_t)(row + 8) * N + col) = h23;
                *(uint32_t*)(Cl + (size_t)(row + 8) * N + col) = l23;
            } else {
                *(float2*)(C + (size_t)row * N + col) =
                    make_float2(acc[mt][nt][0], acc[mt][nt][1]);
                *(float2*)(C + (size_t)(row + 8) * N + col) =
                    make_float2(acc[mt][nt][2], acc[mt][nt][3]);
            }
        }
    }
}

#define GEMM_SMEM_192 (2 * (2 * 128 * RSTRIDE + 2 * 192 * RSTRIDE))   // 184320
#define GEMM_SMEM_256 (2 * (2 * 128 * RSTRIDE + 2 * 256 * RSTRIDE))   // 221184

// ---------------------------------------------------------------------------
// HMMA causal flash attention (R7 proven version).
// ---------------------------------------------------------------------------
#define A_OFF_QH 0
#define A_OFF_QL 18432
#define A_KV0 36864
#define A_KVSTAGE 36864          // Kh(9216) Kl(9216) Vh(9216) Vl(9216)
#define ATT_SMEM (A_KV0 + 3 * A_KVSTAGE)

__global__ void __launch_bounds__(256, 1)
attn_mma(const __nv_bfloat16* __restrict__ qkvh, const __nv_bfloat16* __restrict__ qkvl,
         __nv_bfloat16* __restrict__ Oh, __nv_bfloat16* __restrict__ Ol) {
    extern __shared__ char smem[];
    const uint32_t sb = smem_u32(smem);
    const int tid = threadIdx.x;
    const int warp = tid >> 5, lane = tid & 31;
    const int qt = 7 - blockIdx.x;
    const int b = blockIdx.y >> 4, h = blockIdx.y & 15;
    const int qrow0 = qt * 128;
    const size_t rowbase = (size_t)b * SS;
    const int jlast = 2 * qt + 1;

#pragma unroll
    for (int i = 0; i < 4; i++) {
        const int idx = tid + i * 256;
        const int row = idx >> 3;
        const int c8 = (idx & 7) * 8;
        const size_t g = (rowbase + qrow0 + row) * 3072 + h * DH + c8;
        const uint32_t so = sb + (uint32_t)row * RSTRIDE + (uint32_t)c8 * 2;
        CP_ASYNC16(so + A_OFF_QH, qkvh + g);
        CP_ASYNC16(so + A_OFF_QL, qkvl + g);
    }
    auto issue_kv = [&](int j) {
        const uint32_t so = sb + A_KV0 + (uint32_t)(j % 3) * A_KVSTAGE;
#pragma unroll
        for (int i = 0; i < 2; i++) {
            const int idx = tid + i * 256;
            const int row = idx >> 3;
            const int c8 = (idx & 7) * 8;
            const size_t g = (rowbase + j * 64 + row) * 3072 + h * DH + c8;
            const uint32_t soff = so + (uint32_t)row * RSTRIDE + (uint32_t)c8 * 2;
            CP_ASYNC16(soff,         qkvh + g + 1024);
            CP_ASYNC16(soff + 9216,  qkvl + g + 1024);
            CP_ASYNC16(soff + 18432, qkvh + g + 2048);
            CP_ASYNC16(soff + 27648, qkvl + g + 2048);
        }
    };
    issue_kv(0); CP_COMMIT();
    if (jlast >= 1) { issue_kv(1); CP_COMMIT(); }

    if (jlast >= 1) { CP_WAIT1(); } else { CP_WAIT0(); }
    __syncthreads();

    uint32_t qh[4][4], ql[4][4];
    {
        const uint32_t qbase = sb + (uint32_t)(warp * 16 + (lane & 15)) * RSTRIDE
                             + (uint32_t)(lane >> 4) * 16;
#pragma unroll
        for (int ks = 0; ks < 4; ks++) {
            LDSM_X4(qh[ks], qbase + A_OFF_QH + ks * 32);
            LDSM_X4(ql[ks], qbase + A_OFF_QL + ks * 32);
        }
    }

    float O[8][4];
#pragma unroll
    for (int dt = 0; dt < 8; dt++)
#pragma unroll
        for (int i = 0; i < 4; i++) O[dt][i] = 0.f;
    float m0 = -1e30f, m1 = -1e30f, l0 = 0.f, l1 = 0.f;

    const int rg0 = qrow0 + warp * 16 + (lane >> 2);
    const float SC = 0.18033688011112042f;     // (1/8) * log2(e)

#pragma unroll 1
    for (int j = 0; j <= jlast; j++) {
        if (j + 2 <= jlast) { issue_kv(j + 2); CP_COMMIT(); }
        if (j + 2 <= jlast)      { CP_WAIT2(); }
        else if (j + 1 <= jlast) { CP_WAIT1(); }
        else                     { CP_WAIT0(); }
        __syncthreads();

        const bool active = (64 * j) <= (qrow0 + warp * 16 + 15);
        if (active) {
            const uint32_t so = sb + A_KV0 + (uint32_t)(j % 3) * A_KVSTAGE;

            float S[8][4];
#pragma unroll
            for (int nt = 0; nt < 8; nt++)
#pragma unroll
                for (int i = 0; i < 4; i++) S[nt][i] = 0.f;

            const uint32_t kbase = so + (uint32_t)(lane & 7) * RSTRIDE
                                 + (uint32_t)(lane >> 3) * 16;
#pragma unroll
            for (int nt = 0; nt < 8; nt++) {
                const uint32_t ka = kbase + nt * 8 * RSTRIDE;
                uint32_t kh0[4], kh1[4], kl0[4], kl1[4];
                LDSM_X4(kh0, ka);          LDSM_X4(kh1, ka + 64);
                LDSM_X4(kl0, ka + 9216);   LDSM_X4(kl1, ka + 9216 + 64);
                MMA16816(S[nt], qh[0], kh0[0], kh0[1]);
                MMA16816(S[nt], qh[1], kh0[2], kh0[3]);
                MMA16816(S[nt], qh[2], kh1[0], kh1[1]);
                MMA16816(S[nt], qh[3], kh1[2], kh1[3]);
                MMA16816(S[nt], qh[0], kl0[0], kl0[1]);
                MMA16816(S[nt], qh[1], kl0[2], kl0[3]);
                MMA16816(S[nt], qh[2], kl1[0], kl1[1]);
                MMA16816(S[nt], qh[3], kl1[2], kl1[3]);
                MMA16816(S[nt], ql[0], kh0[0], kh0[1]);
                MMA16816(S[nt], ql[1], kh0[2], kh0[3]);
                MMA16816(S[nt], ql[2], kh1[0], kh1[1]);
                MMA16816(S[nt], ql[3], kh1[2], kh1[3]);
            }

            const bool needmask = (j >= 2 * qt);
            float mx0 = -1e30f, mx1 = -1e30f;
#pragma unroll
            for (int nt = 0; nt < 8; nt++) {
                float t0 = S[nt][0] * SC, t1 = S[nt][1] * SC;
                float t2 = S[nt][2] * SC, t3 = S[nt][3] * SC;
                if (needmask) {
                    const int col = 64 * j + 8 * nt + 2 * (lane & 3);
                    if (col > rg0)         t0 = -1e30f;
                    if (col + 1 > rg0)     t1 = -1e30f;
                    if (col > rg0 + 8)     t2 = -1e30f;
                    if (col + 1 > rg0 + 8) t3 = -1e30f;
                }
                S[nt][0] = t0; S[nt][1] = t1; S[nt][2] = t2; S[nt][3] = t3;
                mx0 = fmaxf(mx0, fmaxf(t0, t1));
                mx1 = fmaxf(mx1, fmaxf(t2, t3));
            }
            mx0 = fmaxf(mx0, __shfl_xor_sync(0xffffffffu, mx0, 1));
            mx0 = fmaxf(mx0, __shfl_xor_sync(0xffffffffu, mx0, 2));
            mx1 = fmaxf(mx1, __shfl_xor_sync(0xffffffffu, mx1, 1));
            mx1 = fmaxf(mx1, __shfl_xor_sync(0xffffffffu, mx1, 2));

            const float mn0 = fmaxf(m0, mx0), mn1 = fmaxf(m1, mx1);
            const float cr0 = ex2(m0 - mn0), cr1 = ex2(m1 - mn1);
            m0 = mn0; m1 = mn1;

            float ls0 = 0.f, ls1 = 0.f;
#pragma unroll
            for (int nt = 0; nt < 8; nt++) {
                const float p0 = ex2(S[nt][0] - m0), p1 = ex2(S[nt][1] - m0);
                const float p2 = ex2(S[nt][2] - m1), p3 = ex2(S[nt][3] - m1);
                S[nt][0] = p0; S[nt][1] = p1; S[nt][2] = p2; S[nt][3] = p3;
                ls0 += p0 + p1;
                ls1 += p2 + p3;
            }
            ls0 += __shfl_xor_sync(0xffffffffu, ls0, 1);
            ls0 += __shfl_xor_sync(0xffffffffu, ls0, 2);
            ls1 += __shfl_xor_sync(0xffffffffu, ls1, 1);
            ls1 += __shfl_xor_sync(0xffffffffu, ls1, 2);
            l0 = l0 * cr0 + ls0;
            l1 = l1 * cr1 + ls1;

#pragma unroll
            for (int dt = 0; dt < 8; dt++) {
                O[dt][0] *= cr0; O[dt][1] *= cr0;
                O[dt][2] *= cr1; O[dt][3] *= cr1;
            }

            uint32_t ph[4][4], pl[4][4];
#pragma unroll
            for (int ks = 0; ks < 4; ks++) {
                split2(S[2 * ks][0],     S[2 * ks][1],     ph[ks][0], pl[ks][0]);
                split2(S[2 * ks][2],     S[2 * ks][3],     ph[ks][1], pl[ks][1]);
                split2(S[2 * ks + 1][0], S[2 * ks + 1][1], ph[ks][2], pl[ks][2]);
                split2(S[2 * ks + 1][2], S[2 * ks + 1][3], ph[ks][3], pl[ks][3]);
            }

            const uint32_t vbase = so + 18432 + (uint32_t)lane * RSTRIDE;
#pragma unroll
            for (int dt = 0; dt < 8; dt++) {
                const uint32_t va = vbase + dt * 16;
                uint32_t vh0[4], vh1[4], vl0[4], vl1[4];
                LDSM_X4_T(vh0, va);                 LDSM_X4_T(vh1, va + 32 * RSTRIDE);
                LDSM_X4_T(vl0, va + 9216);          LDSM_X4_T(vl1, va + 9216 + 32 * RSTRIDE);
                MMA16816(O[dt], ph[0], vh0[0], vh0[1]);
                MMA16816(O[dt], ph[1], vh0[2], vh0[3]);
                MMA16816(O[dt], ph[2], vh1[0], vh1[1]);
                MMA16816(O[dt], ph[3], vh1[2], vh1[3]);
                MMA16816(O[dt], ph[0], vl0[0], vl0[1]);
                MMA16816(O[dt], ph[1], vl0[2], vl0[3]);
                MMA16816(O[dt], ph[2], vl1[0], vl1[1]);
                MMA16816(O[dt], ph[3], vl1[2], vl1[3]);
                MMA16816(O[dt], pl[0], vh0[0], vh0[1]);
                MMA16816(O[dt], pl[1], vh0[2], vh0[3]);
                MMA16816(O[dt], pl[2], vh1[0], vh1[1]);
                MMA16816(O[dt], pl[3], vh1[2], vh1[3]);
            }
        }
        __syncthreads();
    }

    const float inv0 = 1.f / l0, inv1 = 1.f / l1;
    const size_t row0 = rowbase + qrow0 + warp * 16 + (lane >> 2);
    const size_t row1 = row0 + 8;
#pragma unroll
    for (int dt = 0; dt < 8; dt++) {
        const int col = h * DH + dt * 8 + 2 * (lane & 3);
        uint32_t h01, l01, h23, l23;
        split2(O[dt][0] * inv0, O[dt][1] * inv0, h01, l01);
        split2(O[dt][2] * inv1, O[dt][3] * inv1, h23, l23);
        *(uint32_t*)(Oh + row0 * DD + col) = h01;
        *(uint32_t*)(Ol + row0 * DD + col) = l01;
        *(uint32_t*)(Oh + row1 * DD + col) = h23;
        *(uint32_t*)(Ol + row1 * DD + col) = l23;
    }
}

// ---------------------------------------------------------------------------
extern "C" void kernel_launch(void* const* d_in, const int* in_sizes, int n_in,
                              void* d_out, int out_size) {
    const float* x     = (const float*)d_in[0];   // [8,1024,1024]
    const float* w_qkv = (const float*)d_in[2];   // [1024,3072]
    const float* w_out = (const float*)d_in[3];   // [1024,1024]
    float* out = (float*)d_out;

    __nv_bfloat16 *wqh, *wql, *woh, *wol, *ah, *al, *qkvh, *qkvl;
    cudaGetSymbolAddress((void**)&wqh, g_wqkv_h);
    cudaGetSymbolAddress((void**)&wql, g_wqkv_l);
    cudaGetSymbolAddress((void**)&woh, g_wout_h);
    cudaGetSymbolAddress((void**)&wol, g_wout_l);
    cudaGetSymbolAddress((void**)&ah, g_ah);
    cudaGetSymbolAddress((void**)&al, g_al);
    cudaGetSymbolAddress((void**)&qkvh, g_qkvh);
    cudaGetSymbolAddress((void**)&qkvl, g_qkvl);

    cudaFuncSetAttribute((const void*)gemm_mma<192, true>,
                         cudaFuncAttributeMaxDynamicSharedMemorySize, GEMM_SMEM_192);
    cudaFuncSetAttribute((const void*)gemm_mma<256, false>,
                         cudaFuncAttributeMaxDynamicSharedMemorySize, GEMM_SMEM_256);
    cudaFuncSetAttribute(attn_mma, cudaFuncAttributeMaxDynamicSharedMemorySize, ATT_SMEM);

    // 0) weight transpose+split, activation split
    wsplit_kernel<<<dim3(3072 / 32, 1024 / 32), dim3(32, 8)>>>(w_qkv, wqh, wql, 1024, 3072);
    wsplit_kernel<<<dim3(1024 / 32, 1024 / 32), dim3(32, 8)>>>(w_out, woh, wol, 1024, 1024);
    xsplit_kernel<<<(8192 * 1024 / 4) / 256, 256>>>(x, ah, al);

    // 1) QKV projection: 128x192 tiles -> 1024 CTAs (6.92 waves, ~1% tail)
    gemm_mma<192, true><<<dim3(3072 / 192, 8192 / 128), 256, GEMM_SMEM_192>>>(
        ah, al, wqh, wql, nullptr, qkvh, qkvl, 3072);

    // 2) causal flash attention (HMMA) -> split bf16 O
    attn_mma<<<dim3(8, BB * HH), 256, ATT_SMEM>>>(qkvh, qkvl, ah, al);

    // 3) output projection: 128x256 tiles (proven R7 config)
    gemm_mma<256, false><<<dim3(1024 / 256, 8192 / 128), 256, GEMM_SMEM_256>>>(
        ah, al, woh, wol, out, nullptr, nullptr, 1024);
}

// round 15
// speedup vs baseline: 2.3278x; 1.0006x over previous
#include <cuda_runtime.h>
#include <cuda_bf16.h>
#include <cstdint>

#define BB 8
#define SS 1024
#define DD 1024
#define HH 16
#define DH 64
#define KDIM 1024

// ---------------- scratch (__device__ globals; allocation-free rule) --------
__device__ __nv_bfloat16 g_qkvh[(size_t)8192 * 3072]; // qkv hi
__device__ __nv_bfloat16 g_qkvl[(size_t)8192 * 3072]; // qkv lo
__device__ __nv_bfloat16 g_wqkv_h[3072 * 1024];       // W_qkv^T hi [N][K]
__device__ __nv_bfloat16 g_wqkv_l[3072 * 1024];
__device__ __nv_bfloat16 g_wout_h[1024 * 1024];       // W_out^T hi
__device__ __nv_bfloat16 g_wout_l[1024 * 1024];
__device__ __nv_bfloat16 g_ah[(size_t)8192 * 1024];   // activation / attn-out hi
__device__ __nv_bfloat16 g_al[(size_t)8192 * 1024];   // activation / attn-out lo

// ---------------- helpers ---------------------------------------------------
__device__ __forceinline__ uint32_t smem_u32(const void* p) {
    uint32_t a;
    asm("{ .reg .u64 t; cvta.to.shared.u64 t, %1; cvt.u32.u64 %0, t; }"
        : "=r"(a) : "l"(p));
    return a;
}
#define LDSM_X4(r, addr)                                                        \
    asm volatile("ldmatrix.sync.aligned.m8n8.x4.shared.b16 {%0,%1,%2,%3}, [%4];"\
        : "=r"((r)[0]), "=r"((r)[1]), "=r"((r)[2]), "=r"((r)[3]) : "r"(addr))
#define LDSM_X2(r, addr)                                                        \
    asm volatile("ldmatrix.sync.aligned.m8n8.x2.shared.b16 {%0,%1}, [%2];"      \
        : "=r"((r)[0]), "=r"((r)[1]) : "r"(addr))
#define LDSM_X4_T(r, addr)                                                      \
    asm volatile("ldmatrix.sync.aligned.m8n8.x4.trans.shared.b16 {%0,%1,%2,%3}, [%4];"\
        : "=r"((r)[0]), "=r"((r)[1]), "=r"((r)[2]), "=r"((r)[3]) : "r"(addr))
// non-volatile in GEMM path: ptxas may reorder/interleave independent chains
#define MMA16816(d, a, b0, b1)                                                  \
    asm("mma.sync.aligned.m16n8k16.row.col.f32.bf16.bf16.f32 "                  \
        "{%0,%1,%2,%3}, {%4,%5,%6,%7}, {%8,%9}, {%0,%1,%2,%3};"                 \
        : "+f"((d)[0]), "+f"((d)[1]), "+f"((d)[2]), "+f"((d)[3])                \
        : "r"((a)[0]), "r"((a)[1]), "r"((a)[2]), "r"((a)[3]), "r"(b0), "r"(b1))
// volatile variant for the attention kernel (proven R13 behavior, untouched)
#define MMA16816V(d, a, b0, b1)                                                 \
    asm volatile("mma.sync.aligned.m16n8k16.row.col.f32.bf16.bf16.f32 "         \
        "{%0,%1,%2,%3}, {%4,%5,%6,%7}, {%8,%9}, {%0,%1,%2,%3};"                 \
        : "+f"((d)[0]), "+f"((d)[1]), "+f"((d)[2]), "+f"((d)[3])                \
        : "r"((a)[0]), "r"((a)[1]), "r"((a)[2]), "r"((a)[3]), "r"(b0), "r"(b1))
#define CP_ASYNC16(sa, gp)                                                      \
    asm volatile("cp.async.cg.shared.global [%0], [%1], 16;"                    \
                 :: "r"(sa), "l"(gp) : "memory")
#define CP_COMMIT() asm volatile("cp.async.commit_group;" ::: "memory")
#define CP_WAIT0()  asm volatile("cp.async.wait_group 0;" ::: "memory")
#define CP_WAIT1()  asm volatile("cp.async.wait_group 1;" ::: "memory")
#define CP_WAIT2()  asm volatile("cp.async.wait_group 2;" ::: "memory")

__device__ __forceinline__ uint32_t pack_bf16(__nv_bfloat16 a, __nv_bfloat16 b) {
    return (uint32_t)__bfloat16_as_ushort(a) | ((uint32_t)__bfloat16_as_ushort(b) << 16);
}
__device__ __forceinline__ void split1(float v, __nv_bfloat16& h, __nv_bfloat16& l) {
    h = __float2bfloat16(v);
    float hf = __uint_as_float(((uint32_t)__bfloat16_as_ushort(h)) << 16);
    l = __float2bfloat16(v - hf);
}
__device__ __forceinline__ void split2(float a, float b, uint32_t& h, uint32_t& l) {
    __nv_bfloat16 ha, la, hb, lb;
    split1(a, ha, la); split1(b, hb, lb);
    h = pack_bf16(ha, hb); l = pack_bf16(la, lb);
}
__device__ __forceinline__ float ex2(float x) {
    float r;
    asm("ex2.approx.f32 %0, %1;" : "=f"(r) : "f"(x));
    return r;
}

// ---------------------------------------------------------------------------
// Weight pre-pass: W[K,N] fp32 -> H,L [N,K] bf16 (transpose + hi/lo split)
// ---------------------------------------------------------------------------
__global__ void __launch_bounds__(256)
wsplit_kernel(const float* __restrict__ W, __nv_bfloat16* __restrict__ H,
              __nv_bfloat16* __restrict__ L, int K, int N) {
    __shared__ float t[32][33];
    const int tx = threadIdx.x, ty = threadIdx.y;
    const int n0 = blockIdx.x * 32, k0 = blockIdx.y * 32;
#pragma unroll
    for (int i = 0; i < 32; i += 8)
        t[ty + i][tx] = W[(size_t)(k0 + ty + i) * N + n0 + tx];
    __syncthreads();
#pragma unroll
    for (int i = 0; i < 32; i += 8) {
        const int n = ty + i;
        float v = t[tx][n];
        __nv_bfloat16 h, l;
        split1(v, h, l);
        H[(size_t)(n0 + n) * K + k0 + tx] = h;
        L[(size_t)(n0 + n) * K + k0 + tx] = l;
    }
}

// ---------------------------------------------------------------------------
// Activation split: X fp32 [M][K] -> H,L bf16 same layout (elementwise)
// ---------------------------------------------------------------------------
__global__ void __launch_bounds__(256)
xsplit_kernel(const float* __restrict__ X, __nv_bfloat16* __restrict__ H,
              __nv_bfloat16* __restrict__ L) {
    const size_t i4 = (size_t)blockIdx.x * 256 + threadIdx.x;
    float4 v = *(const float4*)(X + i4 * 4);
    __nv_bfloat16 h0, h1, h2, h3, l0, l1, l2, l3;
    split1(v.x, h0, l0); split1(v.y, h1, l1);
    split1(v.z, h2, l2); split1(v.w, h3, l3);
    *(uint2*)(H + i4 * 4) = make_uint2(pack_bf16(h0, h1), pack_bf16(h2, h3));
    *(uint2*)(L + i4 * 4) = make_uint2(pack_bf16(l0, l1), pack_bf16(l2, l3));
}

// ---------------------------------------------------------------------------
// HMMA GEMM (bf16 3-term), templated on CTA N-tile BN (192 or 256).
// 256 threads, 8 warps (2x4), warp tile 64 x (BN/4), KC=64, 2-stage pipeline.
// B loaded per nt-PAIR via ldmatrix.x4; MMAs term-major within pair.
// ---------------------------------------------------------------------------
#define KC 64
#define RSTRIDE 144
#define NCHUNK 16

template <int BN, bool SPLITOUT>
__global__ void __launch_bounds__(256, 1)
gemm_mma(const __nv_bfloat16* __restrict__ Ah, const __nv_bfloat16* __restrict__ Al,
         const __nv_bfloat16* __restrict__ Wh, const __nv_bfloat16* __restrict__ Wl,
         float* __restrict__ C, __nv_bfloat16* __restrict__ Ch,
         __nv_bfloat16* __restrict__ Cl, int N) {
    constexpr int ABYTES = 128 * RSTRIDE;
    constexpr int BBYTES = BN * RSTRIDE;
    constexpr int OFF_AL = ABYTES;
    constexpr int OFF_BH = 2 * ABYTES;
    constexpr int STAGE = 2 * ABYTES + 2 * BBYTES;
    constexpr int NT = BN / 32;                      // n-subtiles per warp (6/8)
    constexpr int NP = NT / 2;                       // nt pairs (3/4)

    extern __shared__ char smem[];
    const uint32_t sb = smem_u32(smem);
    const int tid = threadIdx.x;
    const int warp = tid >> 5, lane = tid & 31;
    const int m0 = blockIdx.y * 128, n0 = blockIdx.x * BN;
    const int wm = (warp >> 2) * 64;
    const int wn = (warp & 3) * (BN / 4);

    float acc[4][NT][4];
#pragma unroll
    for (int mt = 0; mt < 4; mt++)
#pragma unroll
        for (int nt = 0; nt < NT; nt++)
#pragma unroll
            for (int i = 0; i < 4; i++) acc[mt][nt][i] = 0.f;

    auto issue_stage = [&](int s) {
        const uint32_t so = sb + (uint32_t)(s & 1) * STAGE;
        const int k0 = s * KC;
#pragma unroll
        for (int i = 0; i < 4; i++) {
            const int idx = tid + i * 256;
            const int row = idx >> 3;
            const int k8 = (idx & 7) * 8;
            const uint32_t soff = so + (uint32_t)row * RSTRIDE + (uint32_t)k8 * 2;
            const size_t ga = (size_t)(m0 + row) * KDIM + k0 + k8;
            CP_ASYNC16(soff,          Ah + ga);
            CP_ASYNC16(soff + OFF_AL, Al + ga);
        }
#pragma unroll
        for (int i = 0; i < BN / 32; i++) {
            const int idx = tid + i * 256;
            const int row = idx >> 3;
            const int k8 = (idx & 7) * 8;
            const uint32_t soff = so + OFF_BH + (uint32_t)row * RSTRIDE + (uint32_t)k8 * 2;
            const size_t gb = (size_t)(n0 + row) * KDIM + k0 + k8;
            CP_ASYNC16(soff, Wh + gb);
            CP_ASYNC16(soff + BBYTES, Wl + gb);
        }
    };

    issue_stage(0); CP_COMMIT();
    issue_stage(1); CP_COMMIT();

#pragma unroll 1
    for (int c = 0; c < NCHUNK; c++) {
        if (c == NCHUNK - 1) { CP_WAIT0(); } else { CP_WAIT1(); }
        __syncthreads();

        const uint32_t cur = (uint32_t)(c & 1) * STAGE;
        const uint32_t abase = sb + cur + (uint32_t)(wm + (lane & 15)) * RSTRIDE
                             + (uint32_t)(lane >> 4) * 16;
        // B pair base: 4 ldmatrix address groups cover {nt, col0/col16, nt+1}
        const uint32_t bpbase = sb + cur + OFF_BH
                              + (uint32_t)(wn + ((lane >> 4) & 1) * 8 + (lane & 7)) * RSTRIDE
                              + (uint32_t)((lane >> 3) & 1) * 16;
#pragma unroll
        for (int k16 = 0; k16 < 4; k16++) {
            uint32_t ah4[4][4], al4[4][4];
#pragma unroll
            for (int mt = 0; mt < 4; mt++) {
                const uint32_t aa = abase + mt * 16 * RSTRIDE + k16 * 32;
                LDSM_X4(ah4[mt], aa);
                LDSM_X4(al4[mt], aa + OFF_AL);
            }
#pragma unroll
            for (int p = 0; p < NP; p++) {
                // one x4 per limb loads both nt=2p and nt=2p+1 B frags
                uint32_t bh[4], bl[4];
                const uint32_t ba = bpbase + p * 16 * RSTRIDE + k16 * 32;
                LDSM_X4(bh, ba);
                LDSM_X4(bl, ba + BBYTES);
                const int n0t = 2 * p, n1t = 2 * p + 1;
                // term-major: reuse distance 8 independent MMAs
#pragma unroll
                for (int mt = 0; mt < 4; mt++) MMA16816(acc[mt][n0t], ah4[mt], bh[0], bh[1]);
#pragma unroll
                for (int mt = 0; mt < 4; mt++) MMA16816(acc[mt][n1t], ah4[mt], bh[2], bh[3]);
#pragma unroll
                for (int mt = 0; mt < 4; mt++) MMA16816(acc[mt][n0t], ah4[mt], bl[0], bl[1]);
#pragma unroll
                for (int mt = 0; mt < 4; mt++) MMA16816(acc[mt][n1t], ah4[mt], bl[2], bl[3]);
#pragma unroll
                for (int mt = 0; mt < 4; mt++) MMA16816(acc[mt][n0t], al4[mt], bh[0], bh[1]);
#pragma unroll
                for (int mt = 0; mt < 4; mt++) MMA16816(acc[mt][n1t], al4[mt], bh[2], bh[3]);
            }
        }
        __syncthreads();
        if (c + 2 < NCHUNK) { issue_stage(c + 2); CP_COMMIT(); }
    }

#pragma unroll
    for (int mt = 0; mt < 4; mt++) {
        const int row = m0 + wm + mt * 16 + (lane >> 2);
#pragma unroll
        for (int nt = 0; nt < NT; nt++) {
            const int col = n0 + wn + nt * 8 + (lane & 3) * 2;
            if (SPLITOUT) {
                uint32_t h01, l01, h23, l23;
                split2(acc[mt][nt][0], acc[mt][nt][1], h01, l01);
                split2(acc[mt][nt][2], acc[mt][nt][3], h23, l23);
                *(uint32_t*)(Ch + (size_t)row * N + col) = h01;
                *(uint32_t*)(Cl + (size_t)row * N + col) = l01;
                *(uint32_t*)(Ch + (size_t)(row + 8) * N + col) = h23;
                *(uint32_t*)(Cl + (size_t)(row + 8) * N + col) = l23;
            } else {
                *(float2*)(C + (size_t)row * N + col) =
                    make_float2(acc[mt][nt][0], acc[mt][nt][1]);
                *(float2*)(C + (size_t)(row + 8) * N + col) =
                    make_float2(acc[mt][nt][2], acc[mt][nt][3]);
            }
        }
    }
}

#define GEMM_SMEM_192 (2 * (2 * 128 * RSTRIDE + 2 * 192 * RSTRIDE))
#define GEMM_SMEM_256 (2 * (2 * 128 * RSTRIDE + 2 * 256 * RSTRIDE))

// ---------------------------------------------------------------------------
// HMMA causal flash attention (R13 proven version, volatile MMAs).
// ---------------------------------------------------------------------------
#define A_OFF_QH 0
#define A_OFF_QL 18432
#define A_KV0 36864
#define A_KVSTAGE 36864
#define ATT_SMEM (A_KV0 + 3 * A_KVSTAGE)

__global__ void __launch_bounds__(256, 1)
attn_mma(const __nv_bfloat16* __restrict__ qkvh, const __nv_bfloat16* __restrict__ qkvl,
         __nv_bfloat16* __restrict__ Oh, __nv_bfloat16* __restrict__ Ol) {
    extern __shared__ char smem[];
    const uint32_t sb = smem_u32(smem);
    const int tid = threadIdx.x;
    const int warp = tid >> 5, lane = tid & 31;
    const int qt = 7 - blockIdx.x;
    const int b = blockIdx.y >> 4, h = blockIdx.y & 15;
    const int qrow0 = qt * 128;
    const size_t rowbase = (size_t)b * SS;
    const int jlast = 2 * qt + 1;

#pragma unroll
    for (int i = 0; i < 4; i++) {
        const int idx = tid + i * 256;
        const int row = idx >> 3;
        const int c8 = (idx & 7) * 8;
        const size_t g = (rowbase + qrow0 + row) * 3072 + h * DH + c8;
        const uint32_t so = sb + (uint32_t)row * RSTRIDE + (uint32_t)c8 * 2;
        CP_ASYNC16(so + A_OFF_QH, qkvh + g);
        CP_ASYNC16(so + A_OFF_QL, qkvl + g);
    }
    auto issue_kv = [&](int j) {
        const uint32_t so = sb + A_KV0 + (uint32_t)(j % 3) * A_KVSTAGE;
#pragma unroll
        for (int i = 0; i < 2; i++) {
            const int idx = tid + i * 256;
            const int row = idx >> 3;
            const int c8 = (idx & 7) * 8;
            const size_t g = (rowbase + j * 64 + row) * 3072 + h * DH + c8;
            const uint32_t soff = so + (uint32_t)row * RSTRIDE + (uint32_t)c8 * 2;
            CP_ASYNC16(soff,         qkvh + g + 1024);
            CP_ASYNC16(soff + 9216,  qkvl + g + 1024);
            CP_ASYNC16(soff + 18432, qkvh + g + 2048);
            CP_ASYNC16(soff + 27648, qkvl + g + 2048);
        }
    };
    issue_kv(0); CP_COMMIT();
    if (jlast >= 1) { issue_kv(1); CP_COMMIT(); }

    if (jlast >= 1) { CP_WAIT1(); } else { CP_WAIT0(); }
    __syncthreads();

    uint32_t qh[4][4], ql[4][4];
    {
        const uint32_t qbase = sb + (uint32_t)(warp * 16 + (lane & 15)) * RSTRIDE
                             + (uint32_t)(lane >> 4) * 16;
#pragma unroll
        for (int ks = 0; ks < 4; ks++) {
            LDSM_X4(qh[ks], qbase + A_OFF_QH + ks * 32);
            LDSM_X4(ql[ks], qbase + A_OFF_QL + ks * 32);
        }
    }

    float O[8][4];
#pragma unroll
    for (int dt = 0; dt < 8; dt++)
#pragma unroll
        for (int i = 0; i < 4; i++) O[dt][i] = 0.f;
    float m0 = -1e30f, m1 = -1e30f, l0 = 0.f, l1 = 0.f;

    const int rg0 = qrow0 + warp * 16 + (lane >> 2);
    const float SC = 0.18033688011112042f;

#pragma unroll 1
    for (int j = 0; j <= jlast; j++) {
        if (j + 2 <= jlast) { issue_kv(j + 2); CP_COMMIT(); }
        if (j + 2 <= jlast)      { CP_WAIT2(); }
        else if (j + 1 <= jlast) { CP_WAIT1(); }
        else                     { CP_WAIT0(); }
        __syncthreads();

        const bool active = (64 * j) <= (qrow0 + warp * 16 + 15);
        if (active) {
            const uint32_t so = sb + A_KV0 + (uint32_t)(j % 3) * A_KVSTAGE;

            float S[8][4];
#pragma unroll
            for (int nt = 0; nt < 8; nt++)
#pragma unroll
                for (int i = 0; i < 4; i++) S[nt][i] = 0.f;

            const uint32_t kbase = so + (uint32_t)(lane & 7) * RSTRIDE
                                 + (uint32_t)(lane >> 3) * 16;
#pragma unroll
            for (int nt = 0; nt < 8; nt++) {
                const uint32_t ka = kbase + nt * 8 * RSTRIDE;
                uint32_t kh0[4], kh1[4], kl0[4], kl1[4];
                LDSM_X4(kh0, ka);          LDSM_X4(kh1, ka + 64);
                LDSM_X4(kl0, ka + 9216);   LDSM_X4(kl1, ka + 9216 + 64);
                MMA16816V(S[nt], qh[0], kh0[0], kh0[1]);
                MMA16816V(S[nt], qh[1], kh0[2], kh0[3]);
                MMA16816V(S[nt], qh[2], kh1[0], kh1[1]);
                MMA16816V(S[nt], qh[3], kh1[2], kh1[3]);
                MMA16816V(S[nt], qh[0], kl0[0], kl0[1]);
                MMA16816V(S[nt], qh[1], kl0[2], kl0[3]);
                MMA16816V(S[nt], qh[2], kl1[0], kl1[1]);
                MMA16816V(S[nt], qh[3], kl1[2], kl1[3]);
                MMA16816V(S[nt], ql[0], kh0[0], kh0[1]);
                MMA16816V(S[nt], ql[1], kh0[2], kh0[3]);
                MMA16816V(S[nt], ql[2], kh1[0], kh1[1]);
                MMA16816V(S[nt], ql[3], kh1[2], kh1[3]);
            }

            const bool needmask = (j >= 2 * qt);
            float mx0 = -1e30f, mx1 = -1e30f;
#pragma unroll
            for (int nt = 0; nt < 8; nt++) {
                float t0 = S[nt][0] * SC, t1 = S[nt][1] * SC;
                float t2 = S[nt][2] * SC, t3 = S[nt][3] * SC;
                if (needmask) {
                    const int col = 64 * j + 8 * nt + 2 * (lane & 3);
                    if (col > rg0)         t0 = -1e30f;
                    if (col + 1 > rg0)     t1 = -1e30f;
                    if (col > rg0 + 8)     t2 = -1e30f;
                    if (col + 1 > rg0 + 8) t3 = -1e30f;
                }
                S[nt][0] = t0; S[nt][1] = t1; S[nt][2] = t2; S[nt][3] = t3;
                mx0 = fmaxf(mx0, fmaxf(t0, t1));
                mx1 = fmaxf(mx1, fmaxf(t2, t3));
            }
            mx0 = fmaxf(mx0, __shfl_xor_sync(0xffffffffu, mx0, 1));
            mx0 = fmaxf(mx0, __shfl_xor_sync(0xffffffffu, mx0, 2));
            mx1 = fmaxf(mx1, __shfl_xor_sync(0xffffffffu, mx1, 1));
            mx1 = fmaxf(mx1, __shfl_xor_sync(0xffffffffu, mx1, 2));

            const float mn0 = fmaxf(m0, mx0), mn1 = fmaxf(m1, mx1);
            const float cr0 = ex2(m0 - mn0), cr1 = ex2(m1 - mn1);
            m0 = mn0; m1 = mn1;

            float ls0 = 0.f, ls1 = 0.f;
#pragma unroll
            for (int nt = 0; nt < 8; nt++) {
                const float p0 = ex2(S[nt][0] - m0), p1 = ex2(S[nt][1] - m0);
                const float p2 = ex2(S[nt][2] - m1), p3 = ex2(S[nt][3] - m1);
                S[nt][0] = p0; S[nt][1] = p1; S[nt][2] = p2; S[nt][3] = p3;
                ls0 += p0 + p1;
                ls1 += p2 + p3;
            }
            ls0 += __shfl_xor_sync(0xffffffffu, ls0, 1);
            ls0 += __shfl_xor_sync(0xffffffffu, ls0, 2);
            ls1 += __shfl_xor_sync(0xffffffffu, ls1, 1);
            ls1 += __shfl_xor_sync(0xffffffffu, ls1, 2);
            l0 = l0 * cr0 + ls0;
            l1 = l1 * cr1 + ls1;

#pragma unroll
            for (int dt = 0; dt < 8; dt++) {
                O[dt][0] *= cr0; O[dt][1] *= cr0;
                O[dt][2] *= cr1; O[dt][3] *= cr1;
            }

            uint32_t ph[4][4], pl[4][4];
#pragma unroll
            for (int ks = 0; ks < 4; ks++) {
                split2(S[2 * ks][0],     S[2 * ks][1],     ph[ks][0], pl[ks][0]);
                split2(S[2 * ks][2],     S[2 * ks][3],     ph[ks][1], pl[ks][1]);
                split2(S[2 * ks + 1][0], S[2 * ks + 1][1], ph[ks][2], pl[ks][2]);
                split2(S[2 * ks + 1][2], S[2 * ks + 1][3], ph[ks][3], pl[ks][3]);
            }

            const uint32_t vbase = so + 18432 + (uint32_t)lane * RSTRIDE;
#pragma unroll
            for (int dt = 0; dt < 8; dt++) {
                const uint32_t va = vbase + dt * 16;
                uint32_t vh0[4], vh1[4], vl0[4], vl1[4];
                LDSM_X4_T(vh0, va);                 LDSM_X4_T(vh1, va + 32 * RSTRIDE);
                LDSM_X4_T(vl0, va + 9216);          LDSM_X4_T(vl1, va + 9216 + 32 * RSTRIDE);
                MMA16816V(O[dt], ph[0], vh0[0], vh0[1]);
                MMA16816V(O[dt], ph[1], vh0[2], vh0[3]);
                MMA16816V(O[dt], ph[2], vh1[0], vh1[1]);
                MMA16816V(O[dt], ph[3], vh1[2], vh1[3]);
                MMA16816V(O[dt], ph[0], vl0[0], vl0[1]);
                MMA16816V(O[dt], ph[1], vl0[2], vl0[3]);
                MMA16816V(O[dt], ph[2], vl1[0], vl1[1]);
                MMA16816V(O[dt], ph[3], vl1[2], vl1[3]);
                MMA16816V(O[dt], pl[0], vh0[0], vh0[1]);
                MMA16816V(O[dt], pl[1], vh0[2], vh0[3]);
                MMA16816V(O[dt], pl[2], vh1[0], vh1[1]);
                MMA16816V(O[dt], pl[3], vh1[2], vh1[3]);
            }
        }
        __syncthreads();
    }

    const float inv0 = 1.f / l0, inv1 = 1.f / l1;
    const size_t row0 = rowbase + qrow0 + warp * 16 + (lane >> 2);
    const size_t row1 = row0 + 8;
#pragma unroll
    for (int dt = 0; dt < 8; dt++) {
        const int col = h * DH + dt * 8 + 2 * (lane & 3);
        uint32_t h01, l01, h23, l23;
        split2(O[dt][0] * inv0, O[dt][1] * inv0, h01, l01);
        split2(O[dt][2] * inv1, O[dt][3] * inv1, h23, l23);
        *(uint32_t*)(Oh + row0 * DD + col) = h01;
        *(uint32_t*)(Ol + row0 * DD + col) = l01;
        *(uint32_t*)(Oh + row1 * DD + col) = h23;
        *(uint32_t*)(Ol + row1 * DD + col) = l23;
    }
}

// ---------------------------------------------------------------------------
extern "C" void kernel_launch(void* const* d_in, const int* in_sizes, int n_in,
                              void* d_out, int out_size) {
    const float* x     = (const float*)d_in[0];
    const float* w_qkv = (const float*)d_in[2];
    const float* w_out = (const float*)d_in[3];
    float* out = (float*)d_out;

    __nv_bfloat16 *wqh, *wql, *woh, *wol, *ah, *al, *qkvh, *qkvl;
    cudaGetSymbolAddress((void**)&wqh, g_wqkv_h);
    cudaGetSymbolAddress((void**)&wql, g_wqkv_l);
    cudaGetSymbolAddress((void**)&woh, g_wout_h);
    cudaGetSymbolAddress((void**)&wol, g_wout_l);
    cudaGetSymbolAddress((void**)&ah, g_ah);
    cudaGetSymbolAddress((void**)&al, g_al);
    cudaGetSymbolAddress((void**)&qkvh, g_qkvh);
    cudaGetSymbolAddress((void**)&qkvl, g_qkvl);

    cudaFuncSetAttribute((const void*)gemm_mma<192, true>,
                         cudaFuncAttributeMaxDynamicSharedMemorySize, GEMM_SMEM_192);
    cudaFuncSetAttribute((const void*)gemm_mma<256, false>,
                         cudaFuncAttributeMaxDynamicSharedMemorySize, GEMM_SMEM_256);
    cudaFuncSetAttribute(attn_mma, cudaFuncAttributeMaxDynamicSharedMemorySize, ATT_SMEM);

    // 0) weight transpose+split, activation split
    wsplit_kernel<<<dim3(3072 / 32, 1024 / 32), dim3(32, 8)>>>(w_qkv, wqh, wql, 1024, 3072);
    wsplit_kernel<<<dim3(1024 / 32, 1024 / 32), dim3(32, 8)>>>(w_out, woh, wol, 1024, 1024);
    xsplit_kernel<<<(8192 * 1024 / 4) / 256, 256>>>(x, ah, al);

    // 1) QKV projection: 128x192 tiles -> 1024 CTAs (~1% wave tail)
    gemm_mma<192, true><<<dim3(3072 / 192, 8192 / 128), 256, GEMM_SMEM_192>>>(
        ah, al, wqh, wql, nullptr, qkvh, qkvl, 3072);

    // 2) causal flash attention (HMMA) -> split bf16 O
    attn_mma<<<dim3(8, BB * HH), 256, ATT_SMEM>>>(qkvh, qkvl, ah, al);

    // 3) output projection: 128x256 tiles
    gemm_mma<256, false><<<dim3(1024 / 256, 8192 / 128), 256, GEMM_SMEM_256>>>(
        ah, al, woh, wol, out, nullptr, nullptr, 1024);
}